// round 6
// baseline (speedup 1.0000x reference)
#include <cuda_runtime.h>
#include <cuda_bf16.h>
#include <math.h>
#include <float.h>
#include <stdint.h>

// Problem constants
#define B_  16
#define S_  128
#define V_  40000
#define D_  768
#define H_  12
#define HD_ 64
#define F_  3072
#define L_  12
#define T_  (B_ * S_)   // 2048 tokens
#define VPAD 40064
#define QKVN 2304       // 3*D combined

typedef __nv_bfloat16 bf16;

// ---------------------------------------------------------------------------
// Scratch (__device__ globals; zero-initialized at load)
// ---------------------------------------------------------------------------
__device__ __align__(16) float g_h   [T_ * D_];
__device__ __align__(16) float g_qkv [T_ * QKVN];
__device__ __align__(16) float g_r   [T_ * D_];
__device__ __align__(16) float g_h1  [T_ * D_];

__device__ __align__(16) bf16 g_hb_hi [T_ * D_];
__device__ __align__(16) bf16 g_hb_lo [T_ * D_];
__device__ __align__(16) bf16 g_ab_hi [T_ * D_];
__device__ __align__(16) bf16 g_ab_lo [T_ * D_];
__device__ __align__(16) bf16 g_h1b_hi[T_ * D_];
__device__ __align__(16) bf16 g_h1b_lo[T_ * D_];
__device__ __align__(16) bf16 g_tb_hi [T_ * F_];
__device__ __align__(16) bf16 g_tb_lo [T_ * F_];

// Prepped weights: W^T bf16 hi/lo, [N][K] K-major
__device__ __align__(16) bf16 g_wqkv_hi[L_ * QKVN * D_];
__device__ __align__(16) bf16 g_wqkv_lo[L_ * QKVN * D_];
__device__ __align__(16) bf16 g_wo_hi [L_ * D_ * D_];
__device__ __align__(16) bf16 g_wo_lo [L_ * D_ * D_];
__device__ __align__(16) bf16 g_w1_hi [L_ * D_ * F_];
__device__ __align__(16) bf16 g_w1_lo [L_ * D_ * F_];
__device__ __align__(16) bf16 g_w2_hi [L_ * D_ * F_];
__device__ __align__(16) bf16 g_w2_lo [L_ * D_ * F_];
__device__ __align__(16) bf16 g_wout_hi[VPAD * D_];   // pad rows stay zero
__device__ __align__(16) bf16 g_wout_lo[VPAD * D_];
__device__ __align__(16) float g_bqkv[L_ * QKVN];

// ---------------------------------------------------------------------------
// Helpers
// ---------------------------------------------------------------------------
__device__ __forceinline__ float gelu_exact(float x) {
    return 0.5f * x * (1.0f + erff(x * 0.70710678118654752440f));
}
__device__ __forceinline__ float warp_sum(float v) {
    #pragma unroll
    for (int o = 16; o > 0; o >>= 1) v += __shfl_xor_sync(0xFFFFFFFFu, v, o);
    return v;
}
__device__ __forceinline__ uint32_t pack_bf2(bf16 a, bf16 b) {
    return (uint32_t)__bfloat16_as_ushort(a) |
           ((uint32_t)__bfloat16_as_ushort(b) << 16);
}
__device__ __forceinline__ void split2(float x, bf16& h, bf16& l) {
    h = __float2bfloat16(x);
    l = __float2bfloat16(x - __bfloat162float(h));
}
__device__ __forceinline__ uint32_t smem_u32(const void* p) {
    uint32_t a;
    asm("{ .reg .u64 t; cvta.to.shared.u64 t, %1; cvt.u32.u64 %0, t; }"
        : "=r"(a) : "l"(p));
    return a;
}
#define SWZ(off) ((off) ^ (((off) >> 3) & 0x70))

__device__ __forceinline__ void cpa16(uint32_t s, const void* g) {
    asm volatile("cp.async.cg.shared.global [%0], [%1], 16;" :: "r"(s), "l"(g));
}
#define CP_COMMIT() asm volatile("cp.async.commit_group;" ::: "memory")
#define CP_WAIT0()  asm volatile("cp.async.wait_group 0;" ::: "memory")
#define CP_WAIT1()  asm volatile("cp.async.wait_group 1;" ::: "memory")

__device__ __forceinline__ void ldsm4(uint32_t (&r)[4], uint32_t addr) {
    asm volatile("ldmatrix.sync.aligned.m8n8.x4.shared.b16 {%0,%1,%2,%3}, [%4];"
        : "=r"(r[0]), "=r"(r[1]), "=r"(r[2]), "=r"(r[3]) : "r"(addr));
}
__device__ __forceinline__ void mma16816(float* d, const uint32_t (&a)[4],
                                         uint32_t b0, uint32_t b1) {
    asm volatile("mma.sync.aligned.m16n8k16.row.col.f32.bf16.bf16.f32 "
        "{%0,%1,%2,%3}, {%4,%5,%6,%7}, {%8,%9}, {%0,%1,%2,%3};"
        : "+f"(d[0]), "+f"(d[1]), "+f"(d[2]), "+f"(d[3])
        : "r"(a[0]), "r"(a[1]), "r"(a[2]), "r"(a[3]), "r"(b0), "r"(b1));
}

// ---------------------------------------------------------------------------
// Weight prep: transpose + hi/lo split. in [K,N] -> out [N,K]
// ---------------------------------------------------------------------------
__global__ void __launch_bounds__(256) prep_w_kernel(
    const float* __restrict__ in, bf16* __restrict__ ohi, bf16* __restrict__ olo,
    int K, int N, long inBatch, int zdiv, long outL, long outZ)
{
    __shared__ float t[32][33];
    const int tx = threadIdx.x, ty = threadIdx.y;
    const int n0 = blockIdx.x * 32, k0 = blockIdx.y * 32;
    const int z = blockIdx.z;
    in += (long)z * inBatch;
    long ob = (long)(z / zdiv) * outL + (long)(z % zdiv) * outZ;
    ohi += ob; olo += ob;
    #pragma unroll
    for (int i = 0; i < 4; i++)
        t[ty + i * 8][tx] = in[(long)(k0 + ty + i * 8) * N + n0 + tx];
    __syncthreads();
    #pragma unroll
    for (int i = 0; i < 4; i++) {
        float x = t[tx][ty + i * 8];
        bf16 hi, lo; split2(x, hi, lo);
        long o = (long)(n0 + ty + i * 8) * K + k0 + tx;
        ohi[o] = hi; olo[o] = lo;
    }
}

__global__ void __launch_bounds__(256) concat_bias_kernel(
    const float* __restrict__ bq, const float* __restrict__ bk,
    const float* __restrict__ bv, float* __restrict__ out)
{
    int l = blockIdx.x;
    for (int i = threadIdx.x; i < D_; i += 256) {
        out[l * QKVN + i]           = bq[l * D_ + i];
        out[l * QKVN + D_ + i]      = bk[l * D_ + i];
        out[l * QKVN + 2 * D_ + i]  = bv[l * D_ + i];
    }
}

// ---------------------------------------------------------------------------
// HMMA GEMM (3-term bf16 split), 3-stage cp.async pipeline, 256 threads.
// MT=256: warps 4x2, warp tile 64x64.  MT=64: warps 2x4, warp tile 32x32.
// smem row = 128B (32 k-elems: hi 64B | lo 64B), SWZ swizzle, K-chunk 32.
// EPI: 0 fp32 acc+bias ; 1 res+acc+bias ; 2 res+gelu(acc+bias) ; 3 bf16 hi/lo
// ---------------------------------------------------------------------------
#define MG_SMEM_256 (3 * (256 * 128 + 16384) + 1024)
#define MG_SMEM_64  (3 * (64 * 128 + 16384) + 1024)

template<int MT, int EPI, bool GUARD>
__global__ void __launch_bounds__(256) mgemm_kernel(
    const bf16* __restrict__ Ahi, const bf16* __restrict__ Alo,
    const bf16* __restrict__ Bhi, const bf16* __restrict__ Blo,
    const float* __restrict__ bias, const float* __restrict__ Res,
    float* __restrict__ C, bf16* __restrict__ Chi, bf16* __restrict__ Clo,
    int K, int N)
{
    constexpr int AJ     = MT / 32;               // A cp.async 16B per thread
    constexpr int MTILES = (MT == 256) ? 4 : 2;   // m16 tiles per warp
    constexpr int NT     = (MT == 256) ? 8 : 4;   // n8 tiles per warp
    constexpr int NLD    = NT / 2;                // B ldsm4 per k-step
    constexpr int STAGE  = MT * 128 + 16384;

    extern __shared__ char dsm[];
    const uint32_t sraw  = smem_u32(dsm);
    const uint32_t sbase = (sraw + 1023u) & ~1023u;

    const int tid  = threadIdx.x;
    const int lane = tid & 31;
    const int wid  = tid >> 5;
    const int row0 = blockIdx.x * MT;
    const int col0 = blockIdx.y * 128;

    // loaders: id -> row (id>>3), sub (id&7); row = 128B = hi(64B)|lo(64B)
    const bf16* Agp[AJ]; uint32_t sAoff[AJ];
    #pragma unroll
    for (int j = 0; j < AJ; j++) {
        int id = tid + j * 256;
        int row = id >> 3, sub = id & 7;
        int half = sub >> 2, koff = (sub & 3) * 8;
        Agp[j] = (half ? Alo : Ahi) + (long)(row0 + row) * K + koff;
        sAoff[j] = SWZ((uint32_t)(row * 128 + sub * 16));
    }
    const bf16* Bgp[4]; uint32_t sBoff[4];
    #pragma unroll
    for (int j = 0; j < 4; j++) {
        int id = tid + j * 256;
        int row = id >> 3, sub = id & 7;
        int half = sub >> 2, koff = (sub & 3) * 8;
        Bgp[j] = (half ? Blo : Bhi) + (long)(col0 + row) * K + koff;
        sBoff[j] = SWZ((uint32_t)(row * 128 + sub * 16));
    }

    float acc[MTILES][NT][4];
    #pragma unroll
    for (int i = 0; i < MTILES; i++)
        #pragma unroll
        for (int j = 0; j < NT; j++)
            #pragma unroll
            for (int c = 0; c < 4; c++) acc[i][j][c] = 0.f;

    const int m0w = (MT == 256) ? (wid & 3) * 64 : (wid & 1) * 32;
    const int n0w = (MT == 256) ? (wid >> 2) * 64 : (wid >> 1) * 32;
    const uint32_t a_off0 = (uint32_t)((m0w + (lane & 15)) * 128 + ((lane >> 4) * 16));
    const uint32_t b_off0 = (uint32_t)((n0w + ((lane >> 4) * 8) + (lane & 7)) * 128
                                       + (((lane >> 3) & 1) * 16));

    const int nch = K / 32;

    // prologue: chunks 0,1 -> stages 0,1
    #pragma unroll
    for (int p = 0; p < 2; p++) {
        uint32_t sb = sbase + p * STAGE;
        const int ko = p * 32;
        #pragma unroll
        for (int j = 0; j < AJ; j++) cpa16(sb + sAoff[j], Agp[j] + ko);
        #pragma unroll
        for (int j = 0; j < 4; j++)
            cpa16(sb + (uint32_t)(MT * 128) + sBoff[j], Bgp[j] + ko);
        CP_COMMIT();
    }

    int stage = 0;
    for (int ch = 0; ch < nch; ch++) {
        if (ch + 1 < nch) { CP_WAIT1(); } else { CP_WAIT0(); }
        __syncthreads();
        if (ch + 2 < nch) {
            int ps = stage + 2; if (ps >= 3) ps -= 3;
            uint32_t sb = sbase + ps * STAGE;
            const int ko = (ch + 2) * 32;
            #pragma unroll
            for (int j = 0; j < AJ; j++) cpa16(sb + sAoff[j], Agp[j] + ko);
            #pragma unroll
            for (int j = 0; j < 4; j++)
                cpa16(sb + (uint32_t)(MT * 128) + sBoff[j], Bgp[j] + ko);
            CP_COMMIT();
        }

        const uint32_t sA = sbase + stage * STAGE;
        const uint32_t sB = sA + (uint32_t)(MT * 128);

        #pragma unroll
        for (int term = 0; term < 3; term++) {
            const uint32_t aoff = (term == 2) ? 64u : 0u;
            const uint32_t boff = (term == 1) ? 64u : 0u;
            #pragma unroll
            for (int ks = 0; ks < 2; ks++) {
                const uint32_t kb = ks * 32;
                uint32_t af[MTILES][4];
                #pragma unroll
                for (int i = 0; i < MTILES; i++)
                    ldsm4(af[i], sA + SWZ(a_off0 + i * 2048 + aoff + kb));
                uint32_t bq[NLD][4];
                #pragma unroll
                for (int np = 0; np < NLD; np++)
                    ldsm4(bq[np], sB + SWZ(b_off0 + np * 2048 + boff + kb));
                #pragma unroll
                for (int mt = 0; mt < MTILES; mt++)
                    #pragma unroll
                    for (int np = 0; np < NLD; np++) {
                        mma16816(acc[mt][2 * np],     af[mt], bq[np][0], bq[np][1]);
                        mma16816(acc[mt][2 * np + 1], af[mt], bq[np][2], bq[np][3]);
                    }
            }
        }
        if (++stage == 3) stage = 0;
    }

    // Epilogue
    #pragma unroll
    for (int mt = 0; mt < MTILES; mt++) {
        const int r0 = row0 + m0w + mt * 16 + (lane >> 2);
        #pragma unroll
        for (int nt = 0; nt < NT; nt++) {
            const int col = col0 + n0w + nt * 8 + (lane & 3) * 2;
            if (GUARD && col >= N) continue;
            const float* a4 = acc[mt][nt];
            float2 bv = *(const float2*)(bias + col);
            float o0x = a4[0] + bv.x, o0y = a4[1] + bv.y;
            float o1x = a4[2] + bv.x, o1y = a4[3] + bv.y;
            const long off0 = (long)r0 * N + col;
            const long off1 = (long)(r0 + 8) * N + col;
            if (EPI == 1) {
                float2 ra = *(const float2*)(Res + off0);
                float2 rb = *(const float2*)(Res + off1);
                o0x += ra.x; o0y += ra.y; o1x += rb.x; o1y += rb.y;
            } else if (EPI == 2) {
                float2 ra = *(const float2*)(Res + off0);
                float2 rb = *(const float2*)(Res + off1);
                o0x = ra.x + gelu_exact(o0x); o0y = ra.y + gelu_exact(o0y);
                o1x = rb.x + gelu_exact(o1x); o1y = rb.y + gelu_exact(o1y);
            }
            if (EPI == 3) {
                bf16 h0, l0, h1, l1;
                split2(o0x, h0, l0); split2(o0y, h1, l1);
                *(uint32_t*)(Chi + off0) = pack_bf2(h0, h1);
                *(uint32_t*)(Clo + off0) = pack_bf2(l0, l1);
                split2(o1x, h0, l0); split2(o1y, h1, l1);
                *(uint32_t*)(Chi + off1) = pack_bf2(h0, h1);
                *(uint32_t*)(Clo + off1) = pack_bf2(l0, l1);
            } else {
                *(float2*)(C + off0) = make_float2(o0x, o0y);
                *(float2*)(C + off1) = make_float2(o1x, o1y);
            }
        }
    }
}

// ---------------------------------------------------------------------------
// Embedding: h fp32 + hi/lo bf16
// ---------------------------------------------------------------------------
__global__ void __launch_bounds__(256) embed_kernel(
    const int* __restrict__ x, const float* __restrict__ bpe,
    const float* __restrict__ pe, float* __restrict__ h,
    bf16* __restrict__ hbh, bf16* __restrict__ hbl)
{
    int t = blockIdx.x;
    int s = t & (S_ - 1);
    long tok = x[t];
    const float* bp = bpe + tok * (long)D_;
    const float* pp = pe + (long)s * D_;
    long rb = (long)t * D_;
    #pragma unroll
    for (int i = 0; i < 3; i++) {
        int c = threadIdx.x + i * 256;
        float v = bp[c] + pp[c];
        h[rb + c] = v;
        bf16 hi, lo; split2(v, hi, lo);
        hbh[rb + c] = hi; hbl[rb + c] = lo;
    }
}

// ---------------------------------------------------------------------------
// Attention: one block per (b,h), 128 threads. qkv combined [T][2304].
// ---------------------------------------------------------------------------
#define ATTN_SMEM ((128 * 64 + 128 * 129) * 4)

__global__ void __launch_bounds__(128) attn_kernel(
    const float* __restrict__ qkv, const int* __restrict__ ignore,
    bf16* __restrict__ ohi, bf16* __restrict__ olo)
{
    extern __shared__ float sm[];
    float* KV = sm;
    float* P  = sm + 128 * 64;
    __shared__ int ig[S_];

    const int bh = blockIdx.x;
    const int b  = bh / H_;
    const int h  = bh % H_;
    const int tid = threadIdx.x;
    const long qbase = (long)b * S_ * QKVN + (long)h * HD_;
    const long kbase = qbase + D_;
    const long vbase = qbase + 2 * D_;

    ig[tid] = ignore[b * S_ + tid];

    #pragma unroll
    for (int i = 0; i < 16; i++) {
        int idx = tid + i * 128;
        int row = idx >> 4;
        int c4  = idx & 15;
        *(float4*)&KV[row * 64 + c4 * 4] =
            *(const float4*)(qkv + kbase + (long)row * QKVN + c4 * 4);
    }
    float qr[64];
    #pragma unroll
    for (int i = 0; i < 16; i++)
        *(float4*)&qr[i * 4] = *(const float4*)(qkv + qbase + (long)tid * QKVN + i * 4);
    __syncthreads();

    float mx = -FLT_MAX;
    for (int kk = 0; kk < S_; kk++) {
        float s = 0.f;
        #pragma unroll
        for (int e = 0; e < 64; e += 4) {
            float4 kv = *(const float4*)&KV[kk * 64 + e];
            s = fmaf(qr[e + 0], kv.x, s);
            s = fmaf(qr[e + 1], kv.y, s);
            s = fmaf(qr[e + 2], kv.z, s);
            s = fmaf(qr[e + 3], kv.w, s);
        }
        bool allowed = (kk <= tid) && (ig[kk] == 0 || kk == tid);
        float val = allowed ? s * 0.125f : -FLT_MAX;
        P[tid * 129 + kk] = val;
        mx = fmaxf(mx, val);
    }
    __syncthreads();

    #pragma unroll
    for (int i = 0; i < 16; i++) {
        int idx = tid + i * 128;
        int row = idx >> 4;
        int c4  = idx & 15;
        *(float4*)&KV[row * 64 + c4 * 4] =
            *(const float4*)(qkv + vbase + (long)row * QKVN + c4 * 4);
    }
    float sum = 0.f;
    for (int kk = 0; kk < S_; kk++) {
        float e = expf(P[tid * 129 + kk] - mx);
        P[tid * 129 + kk] = e;
        sum += e;
    }
    float inv = 1.0f / sum;
    __syncthreads();

    float acc[64] = {};
    for (int kk = 0; kk < S_; kk++) {
        float p = P[tid * 129 + kk];
        #pragma unroll
        for (int e = 0; e < 64; e += 4) {
            float4 vv = *(const float4*)&KV[kk * 64 + e];
            acc[e + 0] = fmaf(p, vv.x, acc[e + 0]);
            acc[e + 1] = fmaf(p, vv.y, acc[e + 1]);
            acc[e + 2] = fmaf(p, vv.z, acc[e + 2]);
            acc[e + 3] = fmaf(p, vv.w, acc[e + 3]);
        }
    }
    const long obase = (long)(b * S_ + tid) * D_ + (long)h * HD_;
    #pragma unroll
    for (int i = 0; i < 32; i++) {
        float v0 = acc[i * 2] * inv, v1 = acc[i * 2 + 1] * inv;
        bf16 h0, l0, h1, l1;
        split2(v0, h0, l0); split2(v1, h1, l1);
        *(uint32_t*)(ohi + obase + i * 2) = pack_bf2(h0, h1);
        *(uint32_t*)(olo + obase + i * 2) = pack_bf2(l0, l1);
    }
}

// ---------------------------------------------------------------------------
// LayerNorm: fp32 out + bf16 hi/lo out
// ---------------------------------------------------------------------------
__global__ void __launch_bounds__(256) ln_kernel(
    const float* __restrict__ x, const float* __restrict__ w,
    const float* __restrict__ b, float* __restrict__ out,
    bf16* __restrict__ obh, bf16* __restrict__ obl)
{
    const int row = blockIdx.x;
    const int tid = threadIdx.x;
    const float* xr = x + (long)row * D_;

    float v[3], s = 0.f, s2 = 0.f;
    #pragma unroll
    for (int i = 0; i < 3; i++) {
        v[i] = xr[tid + i * 256];
        s += v[i];
        s2 = fmaf(v[i], v[i], s2);
    }
    s  = warp_sum(s);
    s2 = warp_sum(s2);
    __shared__ float sh[16];
    int wid = tid >> 5, lane = tid & 31;
    if (lane == 0) { sh[wid] = s; sh[8 + wid] = s2; }
    __syncthreads();
    if (tid == 0) {
        float a = 0.f, a2 = 0.f;
        #pragma unroll
        for (int i = 0; i < 8; i++) { a += sh[i]; a2 += sh[8 + i]; }
        sh[0] = a; sh[1] = a2;
    }
    __syncthreads();
    float mu  = sh[0] * (1.0f / D_);
    float var = sh[1] * (1.0f / D_) - mu * mu;
    float rs  = rsqrtf(var + 1e-5f);
    long rb = (long)row * D_;
    #pragma unroll
    for (int i = 0; i < 3; i++) {
        int c = tid + i * 256;
        float o = (v[i] - mu) * rs * w[c] + b[c];
        out[rb + c] = o;
        bf16 hi, lo; split2(o, hi, lo);
        obh[rb + c] = hi; obl[rb + c] = lo;
    }
}

// ---------------------------------------------------------------------------
// Launch
// ---------------------------------------------------------------------------
extern "C" void kernel_launch(void* const* d_in, const int* in_sizes, int n_in,
                              void* d_out, int out_size)
{
    const int*   x      = (const int*)  d_in[0];
    const int*   ignore = (const int*)  d_in[1];
    const float* bpe    = (const float*)d_in[2];
    const float* pe     = (const float*)d_in[3];
    const float* Wq     = (const float*)d_in[4];
    const float* bq     = (const float*)d_in[5];
    const float* Wk     = (const float*)d_in[6];
    const float* bk     = (const float*)d_in[7];
    const float* Wv     = (const float*)d_in[8];
    const float* bv     = (const float*)d_in[9];
    const float* Wo     = (const float*)d_in[10];
    const float* bo     = (const float*)d_in[11];
    const float* W1     = (const float*)d_in[12];
    const float* b1     = (const float*)d_in[13];
    const float* W2     = (const float*)d_in[14];
    const float* b2     = (const float*)d_in[15];
    const float* ln1w   = (const float*)d_in[16];
    const float* ln1b   = (const float*)d_in[17];
    const float* ln2w   = (const float*)d_in[18];
    const float* ln2b   = (const float*)d_in[19];
    const float* Wout   = (const float*)d_in[20];
    const float* bout   = (const float*)d_in[21];
    float* out = (float*)d_out;

    cudaFuncSetAttribute(attn_kernel,
        cudaFuncAttributeMaxDynamicSharedMemorySize, ATTN_SMEM);
    cudaFuncSetAttribute(mgemm_kernel<256, 0, false>,
        cudaFuncAttributeMaxDynamicSharedMemorySize, MG_SMEM_256);
    cudaFuncSetAttribute(mgemm_kernel<256, 3, false>,
        cudaFuncAttributeMaxDynamicSharedMemorySize, MG_SMEM_256);
    cudaFuncSetAttribute(mgemm_kernel<256, 0, true>,
        cudaFuncAttributeMaxDynamicSharedMemorySize, MG_SMEM_256);
    cudaFuncSetAttribute(mgemm_kernel<64, 1, false>,
        cudaFuncAttributeMaxDynamicSharedMemorySize, MG_SMEM_64);
    cudaFuncSetAttribute(mgemm_kernel<64, 2, false>,
        cudaFuncAttributeMaxDynamicSharedMemorySize, MG_SMEM_64);

    float *h, *qkv, *r, *h1, *bqkv;
    bf16 *hbh, *hbl, *abh, *abl, *h1bh, *h1bl, *tbh, *tbl;
    bf16 *wqkvh, *wqkvl, *woh, *wol, *w1h, *w1l, *w2h, *w2l, *wouth, *woutl;
    cudaGetSymbolAddress((void**)&h,    g_h);
    cudaGetSymbolAddress((void**)&qkv,  g_qkv);
    cudaGetSymbolAddress((void**)&r,    g_r);
    cudaGetSymbolAddress((void**)&h1,   g_h1);
    cudaGetSymbolAddress((void**)&hbh,  g_hb_hi);
    cudaGetSymbolAddress((void**)&hbl,  g_hb_lo);
    cudaGetSymbolAddress((void**)&abh,  g_ab_hi);
    cudaGetSymbolAddress((void**)&abl,  g_ab_lo);
    cudaGetSymbolAddress((void**)&h1bh, g_h1b_hi);
    cudaGetSymbolAddress((void**)&h1bl, g_h1b_lo);
    cudaGetSymbolAddress((void**)&tbh,  g_tb_hi);
    cudaGetSymbolAddress((void**)&tbl,  g_tb_lo);
    cudaGetSymbolAddress((void**)&wqkvh, g_wqkv_hi);
    cudaGetSymbolAddress((void**)&wqkvl, g_wqkv_lo);
    cudaGetSymbolAddress((void**)&woh,  g_wo_hi);
    cudaGetSymbolAddress((void**)&wol,  g_wo_lo);
    cudaGetSymbolAddress((void**)&w1h,  g_w1_hi);
    cudaGetSymbolAddress((void**)&w1l,  g_w1_lo);
    cudaGetSymbolAddress((void**)&w2h,  g_w2_hi);
    cudaGetSymbolAddress((void**)&w2l,  g_w2_lo);
    cudaGetSymbolAddress((void**)&wouth, g_wout_hi);
    cudaGetSymbolAddress((void**)&woutl, g_wout_lo);
    cudaGetSymbolAddress((void**)&bqkv, g_bqkv);

    dim3 pb(32, 8);
    prep_w_kernel<<<dim3(2, 24, L_ * H_), pb>>>(Wq, wqkvh, wqkvl,
        D_, HD_, (long)D_ * HD_, H_, (long)QKVN * D_, (long)HD_ * D_);
    prep_w_kernel<<<dim3(2, 24, L_ * H_), pb>>>(Wk,
        wqkvh + (long)D_ * D_, wqkvl + (long)D_ * D_,
        D_, HD_, (long)D_ * HD_, H_, (long)QKVN * D_, (long)HD_ * D_);
    prep_w_kernel<<<dim3(2, 24, L_ * H_), pb>>>(Wv,
        wqkvh + (long)2 * D_ * D_, wqkvl + (long)2 * D_ * D_,
        D_, HD_, (long)D_ * HD_, H_, (long)QKVN * D_, (long)HD_ * D_);
    prep_w_kernel<<<dim3(24, 24, L_), pb>>>(Wo, woh, wol,
        D_, D_, (long)D_ * D_, 1, (long)D_ * D_, 0);
    prep_w_kernel<<<dim3(96, 24, L_), pb>>>(W1, w1h, w1l,
        D_, F_, (long)D_ * F_, 1, (long)D_ * F_, 0);
    prep_w_kernel<<<dim3(24, 96, L_), pb>>>(W2, w2h, w2l,
        F_, D_, (long)F_ * D_, 1, (long)F_ * D_, 0);
    prep_w_kernel<<<dim3(1250, 24, 1), pb>>>(Wout, wouth, woutl,
        D_, V_, 0, 1, 0, 0);
    concat_bias_kernel<<<L_, 256>>>(bq, bk, bv, bqkv);

    embed_kernel<<<T_, 256>>>(x, bpe, pe, h, hbh, hbl);

    const dim3 gQKV(T_ / 256, QKVN / 128);  // 8 x 18 = 144
    const dim3 gD64(T_ / 64,  D_ / 128);    // 32 x 6 = 192
    const dim3 gF  (T_ / 256, F_ / 128);    // 8 x 24 = 192
    const dim3 gV  (T_ / 256, VPAD / 128);  // 8 x 313 = 2504

    for (int l = 0; l < L_; l++) {
        long wq_off = (long)l * QKVN * D_;
        long wd_off = (long)l * D_ * D_;
        long wf_off = (long)l * D_ * F_;

        // qkv = h @ Wqkv + bqkv
        mgemm_kernel<256, 0, false><<<gQKV, 256, MG_SMEM_256>>>(
            hbh, hbl, wqkvh + wq_off, wqkvl + wq_off, bqkv + (long)l * QKVN,
            nullptr, qkv, nullptr, nullptr, D_, QKVN);

        attn_kernel<<<B_ * H_, 128, ATTN_SMEM>>>(qkv, ignore, abh, abl);

        // r = h + a @ Wo + bo
        mgemm_kernel<64, 1, false><<<gD64, 256, MG_SMEM_64>>>(
            abh, abl, woh + wd_off, wol + wd_off, bo + (long)l * D_,
            h, r, nullptr, nullptr, D_, D_);
        ln_kernel<<<T_, 256>>>(r, ln1w + (long)l * D_, ln1b + (long)l * D_,
                               h1, h1bh, h1bl);
        // t = h1 @ W1 + b1 (bf16-only output)
        mgemm_kernel<256, 3, false><<<gF, 256, MG_SMEM_256>>>(
            h1bh, h1bl, w1h + wf_off, w1l + wf_off, b1 + (long)l * F_,
            nullptr, nullptr, tbh, tbl, D_, F_);
        // r = h1 + gelu(t @ W2 + b2)
        mgemm_kernel<64, 2, false><<<gD64, 256, MG_SMEM_64>>>(
            tbh, tbl, w2h + wf_off, w2l + wf_off, b2 + (long)l * D_,
            h1, r, nullptr, nullptr, F_, D_);
        ln_kernel<<<T_, 256>>>(r, ln2w + (long)l * D_, ln2b + (long)l * D_,
                               h, hbh, hbl);
    }

    // logits = h @ Wout + bout
    mgemm_kernel<256, 0, true><<<gV, 256, MG_SMEM_256>>>(
        hbh, hbl, wouth, woutl, bout, nullptr, out, nullptr, nullptr, D_, V_);
}

// round 7
// speedup vs baseline: 1.0359x; 1.0359x over previous
#include <cuda_runtime.h>
#include <cuda_bf16.h>
#include <math.h>
#include <float.h>
#include <stdint.h>

// Problem constants
#define B_  16
#define S_  128
#define V_  40000
#define D_  768
#define H_  12
#define HD_ 64
#define F_  3072
#define L_  12
#define T_  (B_ * S_)   // 2048 tokens
#define VPAD 40064
#define QKVN 2304       // 3*D combined

typedef __nv_bfloat16 bf16;

// ---------------------------------------------------------------------------
// Scratch (__device__ globals; zero-initialized at load)
// ---------------------------------------------------------------------------
__device__ __align__(16) float g_h   [T_ * D_];
__device__ __align__(16) float g_qkv [T_ * QKVN];
__device__ __align__(16) float g_r   [T_ * D_];
__device__ __align__(16) float g_h1  [T_ * D_];

__device__ __align__(16) bf16 g_hb_hi [T_ * D_];
__device__ __align__(16) bf16 g_hb_lo [T_ * D_];
__device__ __align__(16) bf16 g_ab_hi [T_ * D_];
__device__ __align__(16) bf16 g_ab_lo [T_ * D_];
__device__ __align__(16) bf16 g_h1b_hi[T_ * D_];
__device__ __align__(16) bf16 g_h1b_lo[T_ * D_];
__device__ __align__(16) bf16 g_tb_hi [T_ * F_];
__device__ __align__(16) bf16 g_tb_lo [T_ * F_];

// Prepped weights: W^T bf16 hi/lo, [N][K] K-major
__device__ __align__(16) bf16 g_wqkv_hi[L_ * QKVN * D_];
__device__ __align__(16) bf16 g_wqkv_lo[L_ * QKVN * D_];
__device__ __align__(16) bf16 g_wo_hi [L_ * D_ * D_];
__device__ __align__(16) bf16 g_wo_lo [L_ * D_ * D_];
__device__ __align__(16) bf16 g_w1_hi [L_ * D_ * F_];
__device__ __align__(16) bf16 g_w1_lo [L_ * D_ * F_];
__device__ __align__(16) bf16 g_w2_hi [L_ * D_ * F_];
__device__ __align__(16) bf16 g_w2_lo [L_ * D_ * F_];
__device__ __align__(16) bf16 g_wout_hi[VPAD * D_];   // pad rows stay zero
__device__ __align__(16) bf16 g_wout_lo[VPAD * D_];
__device__ __align__(16) float g_bqkv[L_ * QKVN];

// ---------------------------------------------------------------------------
// Helpers
// ---------------------------------------------------------------------------
__device__ __forceinline__ float gelu_exact(float x) {
    return 0.5f * x * (1.0f + erff(x * 0.70710678118654752440f));
}
__device__ __forceinline__ float warp_sum(float v) {
    #pragma unroll
    for (int o = 16; o > 0; o >>= 1) v += __shfl_xor_sync(0xFFFFFFFFu, v, o);
    return v;
}
__device__ __forceinline__ uint32_t pack_bf2(bf16 a, bf16 b) {
    return (uint32_t)__bfloat16_as_ushort(a) |
           ((uint32_t)__bfloat16_as_ushort(b) << 16);
}
__device__ __forceinline__ void split2(float x, bf16& h, bf16& l) {
    h = __float2bfloat16(x);
    l = __float2bfloat16(x - __bfloat162float(h));
}
__device__ __forceinline__ uint32_t smem_u32(const void* p) {
    uint32_t a;
    asm("{ .reg .u64 t; cvta.to.shared.u64 t, %1; cvt.u32.u64 %0, t; }"
        : "=r"(a) : "l"(p));
    return a;
}
#define SWZ(off) ((off) ^ (((off) >> 3) & 0x70))

__device__ __forceinline__ void cpa16(uint32_t s, const void* g) {
    asm volatile("cp.async.cg.shared.global [%0], [%1], 16;" :: "r"(s), "l"(g));
}
#define CP_COMMIT() asm volatile("cp.async.commit_group;" ::: "memory")
#define CP_WAIT0()  asm volatile("cp.async.wait_group 0;" ::: "memory")

__device__ __forceinline__ void ldsm4(uint32_t (&r)[4], uint32_t addr) {
    asm volatile("ldmatrix.sync.aligned.m8n8.x4.shared.b16 {%0,%1,%2,%3}, [%4];"
        : "=r"(r[0]), "=r"(r[1]), "=r"(r[2]), "=r"(r[3]) : "r"(addr));
}
__device__ __forceinline__ void mma16816(float* d, const uint32_t (&a)[4],
                                         uint32_t b0, uint32_t b1) {
    asm volatile("mma.sync.aligned.m16n8k16.row.col.f32.bf16.bf16.f32 "
        "{%0,%1,%2,%3}, {%4,%5,%6,%7}, {%8,%9}, {%0,%1,%2,%3};"
        : "+f"(d[0]), "+f"(d[1]), "+f"(d[2]), "+f"(d[3])
        : "r"(a[0]), "r"(a[1]), "r"(a[2]), "r"(a[3]), "r"(b0), "r"(b1));
}

// ---------------------------------------------------------------------------
// Weight prep: transpose + hi/lo split. in [K,N] -> out [N,K]
// ---------------------------------------------------------------------------
__global__ void __launch_bounds__(256) prep_w_kernel(
    const float* __restrict__ in, bf16* __restrict__ ohi, bf16* __restrict__ olo,
    int K, int N, long inBatch, int zdiv, long outL, long outZ)
{
    __shared__ float t[32][33];
    const int tx = threadIdx.x, ty = threadIdx.y;
    const int n0 = blockIdx.x * 32, k0 = blockIdx.y * 32;
    const int z = blockIdx.z;
    in += (long)z * inBatch;
    long ob = (long)(z / zdiv) * outL + (long)(z % zdiv) * outZ;
    ohi += ob; olo += ob;
    #pragma unroll
    for (int i = 0; i < 4; i++)
        t[ty + i * 8][tx] = in[(long)(k0 + ty + i * 8) * N + n0 + tx];
    __syncthreads();
    #pragma unroll
    for (int i = 0; i < 4; i++) {
        float x = t[tx][ty + i * 8];
        bf16 hi, lo; split2(x, hi, lo);
        long o = (long)(n0 + ty + i * 8) * K + k0 + tx;
        ohi[o] = hi; olo[o] = lo;
    }
}

__global__ void __launch_bounds__(256) concat_bias_kernel(
    const float* __restrict__ bq, const float* __restrict__ bk,
    const float* __restrict__ bv, float* __restrict__ out)
{
    int l = blockIdx.x;
    for (int i = threadIdx.x; i < D_; i += 256) {
        out[l * QKVN + i]           = bq[l * D_ + i];
        out[l * QKVN + D_ + i]      = bk[l * D_ + i];
        out[l * QKVN + 2 * D_ + i]  = bv[l * D_ + i];
    }
}

// ---------------------------------------------------------------------------
// HMMA GEMM: C = A(bf16 hi/lo) x W(bf16 hi/lo [N][K]) + bias (+res/gelu)
// 3-term split with FRAGMENT REUSE: a_hi shared by t0/t1, b_hi by t0/t2.
// K-chunk 32; double-buffered cp.async; single sync per chunk; 256 threads.
// MT=128: 8 warps 4x2, warp tile 32x64.  MT=64: 8 warps 2x4, warp tile 32x32.
// EPI: 0 fp32 acc+bias ; 1 res+acc+bias ; 2 res+gelu(acc+bias) ; 3 bf16 hi/lo
// ---------------------------------------------------------------------------
#define MG_SMEM_128 (2 * (128 * 128 + 16384) + 1024)
#define MG_SMEM_64  (2 * (64 * 128 + 16384) + 1024)

template<int MT, int EPI, bool GUARD>
__global__ void __launch_bounds__(256) mgemm_kernel(
    const bf16* __restrict__ Ahi, const bf16* __restrict__ Alo,
    const bf16* __restrict__ Bhi, const bf16* __restrict__ Blo,
    const float* __restrict__ bias, const float* __restrict__ Res,
    float* __restrict__ C, bf16* __restrict__ Chi, bf16* __restrict__ Clo,
    int K, int N)
{
    constexpr int AJ  = MT / 32;              // A cp.async 16B per thread
    constexpr int NT  = (MT == 128) ? 8 : 4;  // n8 tiles per warp
    constexpr int NLD = NT / 2;               // B ldsm4 per k-step
    constexpr int STAGE = MT * 128 + 16384;

    extern __shared__ char dsm[];
    const uint32_t sraw  = smem_u32(dsm);
    const uint32_t sbase = (sraw + 1023u) & ~1023u;

    const int tid  = threadIdx.x;
    const int lane = tid & 31;
    const int wid  = tid >> 5;
    const int row0 = blockIdx.x * MT;
    const int col0 = blockIdx.y * 128;

    // loaders: id -> row (id>>3), sub (id&7); row = 128B = hi(64B)|lo(64B)
    const bf16* Agp[AJ]; uint32_t sAoff[AJ];
    #pragma unroll
    for (int j = 0; j < AJ; j++) {
        int id = tid + j * 256;
        int row = id >> 3, sub = id & 7;
        int half = sub >> 2, koff = (sub & 3) * 8;
        Agp[j] = (half ? Alo : Ahi) + (long)(row0 + row) * K + koff;
        sAoff[j] = SWZ((uint32_t)(row * 128 + sub * 16));
    }
    const bf16* Bgp[4]; uint32_t sBoff[4];
    #pragma unroll
    for (int j = 0; j < 4; j++) {
        int id = tid + j * 256;
        int row = id >> 3, sub = id & 7;
        int half = sub >> 2, koff = (sub & 3) * 8;
        Bgp[j] = (half ? Blo : Bhi) + (long)(col0 + row) * K + koff;
        sBoff[j] = SWZ((uint32_t)(row * 128 + sub * 16));
    }

    float acc[2][NT][4];
    #pragma unroll
    for (int i = 0; i < 2; i++)
        #pragma unroll
        for (int j = 0; j < NT; j++)
            #pragma unroll
            for (int c = 0; c < 4; c++) acc[i][j][c] = 0.f;

    const int m0w = (MT == 128) ? (wid & 3) * 32 : (wid & 1) * 32;
    const int n0w = (MT == 128) ? (wid >> 2) * 64 : (wid >> 1) * 32;
    const uint32_t a_off0 = (uint32_t)((m0w + (lane & 15)) * 128 + ((lane >> 4) * 16));
    const uint32_t b_off0 = (uint32_t)((n0w + ((lane >> 4) * 8) + (lane & 7)) * 128
                                       + (((lane >> 3) & 1) * 16));

    const int nch = K / 32;

    // prologue: chunk 0 -> buffer 0
    {
        #pragma unroll
        for (int j = 0; j < AJ; j++) cpa16(sbase + sAoff[j], Agp[j]);
        #pragma unroll
        for (int j = 0; j < 4; j++)
            cpa16(sbase + (uint32_t)(MT * 128) + sBoff[j], Bgp[j]);
        CP_COMMIT();
    }

    for (int ch = 0; ch < nch; ch++) {
        CP_WAIT0();
        __syncthreads();
        if (ch + 1 < nch) {
            uint32_t sb = sbase + ((ch + 1) & 1) * STAGE;
            const int ko = (ch + 1) * 32;
            #pragma unroll
            for (int j = 0; j < AJ; j++) cpa16(sb + sAoff[j], Agp[j] + ko);
            #pragma unroll
            for (int j = 0; j < 4; j++)
                cpa16(sb + (uint32_t)(MT * 128) + sBoff[j], Bgp[j] + ko);
            CP_COMMIT();
        }

        const uint32_t sA = sbase + (ch & 1) * STAGE;
        const uint32_t sB = sA + (uint32_t)(MT * 128);

        #pragma unroll
        for (int ks = 0; ks < 2; ks++) {
            const uint32_t kb = ks * 32;
            // persistent fragments
            uint32_t ah[2][4], bh[NLD][4];
            ldsm4(ah[0], sA + SWZ(a_off0 + kb));
            ldsm4(ah[1], sA + SWZ(a_off0 + 2048 + kb));
            #pragma unroll
            for (int np = 0; np < NLD; np++)
                ldsm4(bh[np], sB + SWZ(b_off0 + np * 2048 + kb));
            // term 0: a_hi x b_hi
            #pragma unroll
            for (int mt = 0; mt < 2; mt++)
                #pragma unroll
                for (int np = 0; np < NLD; np++) {
                    mma16816(acc[mt][2 * np],     ah[mt], bh[np][0], bh[np][1]);
                    mma16816(acc[mt][2 * np + 1], ah[mt], bh[np][2], bh[np][3]);
                }
            // term 1: a_hi x b_lo (transient b_lo)
            {
                uint32_t bl[NLD][4];
                #pragma unroll
                for (int np = 0; np < NLD; np++)
                    ldsm4(bl[np], sB + SWZ(b_off0 + np * 2048 + 64 + kb));
                #pragma unroll
                for (int mt = 0; mt < 2; mt++)
                    #pragma unroll
                    for (int np = 0; np < NLD; np++) {
                        mma16816(acc[mt][2 * np],     ah[mt], bl[np][0], bl[np][1]);
                        mma16816(acc[mt][2 * np + 1], ah[mt], bl[np][2], bl[np][3]);
                    }
            }
            // term 2: a_lo x b_hi (transient a_lo)
            {
                uint32_t al[2][4];
                ldsm4(al[0], sA + SWZ(a_off0 + 64 + kb));
                ldsm4(al[1], sA + SWZ(a_off0 + 2048 + 64 + kb));
                #pragma unroll
                for (int mt = 0; mt < 2; mt++)
                    #pragma unroll
                    for (int np = 0; np < NLD; np++) {
                        mma16816(acc[mt][2 * np],     al[mt], bh[np][0], bh[np][1]);
                        mma16816(acc[mt][2 * np + 1], al[mt], bh[np][2], bh[np][3]);
                    }
            }
        }
    }

    // Epilogue
    #pragma unroll
    for (int mt = 0; mt < 2; mt++) {
        const int r0 = row0 + m0w + mt * 16 + (lane >> 2);
        #pragma unroll
        for (int nt = 0; nt < NT; nt++) {
            const int col = col0 + n0w + nt * 8 + (lane & 3) * 2;
            if (GUARD && col >= N) continue;
            const float* a4 = acc[mt][nt];
            float2 bv = *(const float2*)(bias + col);
            float o0x = a4[0] + bv.x, o0y = a4[1] + bv.y;
            float o1x = a4[2] + bv.x, o1y = a4[3] + bv.y;
            const long off0 = (long)r0 * N + col;
            const long off1 = (long)(r0 + 8) * N + col;
            if (EPI == 1) {
                float2 ra = *(const float2*)(Res + off0);
                float2 rb = *(const float2*)(Res + off1);
                o0x += ra.x; o0y += ra.y; o1x += rb.x; o1y += rb.y;
            } else if (EPI == 2) {
                float2 ra = *(const float2*)(Res + off0);
                float2 rb = *(const float2*)(Res + off1);
                o0x = ra.x + gelu_exact(o0x); o0y = ra.y + gelu_exact(o0y);
                o1x = rb.x + gelu_exact(o1x); o1y = rb.y + gelu_exact(o1y);
            }
            if (EPI == 3) {
                bf16 h0, l0, h1, l1;
                split2(o0x, h0, l0); split2(o0y, h1, l1);
                *(uint32_t*)(Chi + off0) = pack_bf2(h0, h1);
                *(uint32_t*)(Clo + off0) = pack_bf2(l0, l1);
                split2(o1x, h0, l0); split2(o1y, h1, l1);
                *(uint32_t*)(Chi + off1) = pack_bf2(h0, h1);
                *(uint32_t*)(Clo + off1) = pack_bf2(l0, l1);
            } else {
                *(float2*)(C + off0) = make_float2(o0x, o0y);
                *(float2*)(C + off1) = make_float2(o1x, o1y);
            }
        }
    }
}

// ---------------------------------------------------------------------------
// Embedding: h fp32 + hi/lo bf16
// ---------------------------------------------------------------------------
__global__ void __launch_bounds__(256) embed_kernel(
    const int* __restrict__ x, const float* __restrict__ bpe,
    const float* __restrict__ pe, float* __restrict__ h,
    bf16* __restrict__ hbh, bf16* __restrict__ hbl)
{
    int t = blockIdx.x;
    int s = t & (S_ - 1);
    long tok = x[t];
    const float* bp = bpe + tok * (long)D_;
    const float* pp = pe + (long)s * D_;
    long rb = (long)t * D_;
    #pragma unroll
    for (int i = 0; i < 3; i++) {
        int c = threadIdx.x + i * 256;
        float v = bp[c] + pp[c];
        h[rb + c] = v;
        bf16 hi, lo; split2(v, hi, lo);
        hbh[rb + c] = hi; hbl[rb + c] = lo;
    }
}

// ---------------------------------------------------------------------------
// Attention: one block per (b,h), 128 threads. qkv combined [T][2304].
// ---------------------------------------------------------------------------
#define ATTN_SMEM ((128 * 64 + 128 * 129) * 4)

__global__ void __launch_bounds__(128) attn_kernel(
    const float* __restrict__ qkv, const int* __restrict__ ignore,
    bf16* __restrict__ ohi, bf16* __restrict__ olo)
{
    extern __shared__ float sm[];
    float* KV = sm;
    float* P  = sm + 128 * 64;
    __shared__ int ig[S_];

    const int bh = blockIdx.x;
    const int b  = bh / H_;
    const int h  = bh % H_;
    const int tid = threadIdx.x;
    const long qbase = (long)b * S_ * QKVN + (long)h * HD_;
    const long kbase = qbase + D_;
    const long vbase = qbase + 2 * D_;

    ig[tid] = ignore[b * S_ + tid];

    #pragma unroll
    for (int i = 0; i < 16; i++) {
        int idx = tid + i * 128;
        int row = idx >> 4;
        int c4  = idx & 15;
        *(float4*)&KV[row * 64 + c4 * 4] =
            *(const float4*)(qkv + kbase + (long)row * QKVN + c4 * 4);
    }
    float qr[64];
    #pragma unroll
    for (int i = 0; i < 16; i++)
        *(float4*)&qr[i * 4] = *(const float4*)(qkv + qbase + (long)tid * QKVN + i * 4);
    __syncthreads();

    float mx = -FLT_MAX;
    for (int kk = 0; kk < S_; kk++) {
        float s = 0.f;
        #pragma unroll
        for (int e = 0; e < 64; e += 4) {
            float4 kv = *(const float4*)&KV[kk * 64 + e];
            s = fmaf(qr[e + 0], kv.x, s);
            s = fmaf(qr[e + 1], kv.y, s);
            s = fmaf(qr[e + 2], kv.z, s);
            s = fmaf(qr[e + 3], kv.w, s);
        }
        bool allowed = (kk <= tid) && (ig[kk] == 0 || kk == tid);
        float val = allowed ? s * 0.125f : -FLT_MAX;
        P[tid * 129 + kk] = val;
        mx = fmaxf(mx, val);
    }
    __syncthreads();

    #pragma unroll
    for (int i = 0; i < 16; i++) {
        int idx = tid + i * 128;
        int row = idx >> 4;
        int c4  = idx & 15;
        *(float4*)&KV[row * 64 + c4 * 4] =
            *(const float4*)(qkv + vbase + (long)row * QKVN + c4 * 4);
    }
    float sum = 0.f;
    for (int kk = 0; kk < S_; kk++) {
        float e = expf(P[tid * 129 + kk] - mx);
        P[tid * 129 + kk] = e;
        sum += e;
    }
    float inv = 1.0f / sum;
    __syncthreads();

    float acc[64] = {};
    for (int kk = 0; kk < S_; kk++) {
        float p = P[tid * 129 + kk];
        #pragma unroll
        for (int e = 0; e < 64; e += 4) {
            float4 vv = *(const float4*)&KV[kk * 64 + e];
            acc[e + 0] = fmaf(p, vv.x, acc[e + 0]);
            acc[e + 1] = fmaf(p, vv.y, acc[e + 1]);
            acc[e + 2] = fmaf(p, vv.z, acc[e + 2]);
            acc[e + 3] = fmaf(p, vv.w, acc[e + 3]);
        }
    }
    const long obase = (long)(b * S_ + tid) * D_ + (long)h * HD_;
    #pragma unroll
    for (int i = 0; i < 32; i++) {
        float v0 = acc[i * 2] * inv, v1 = acc[i * 2 + 1] * inv;
        bf16 h0, l0, h1, l1;
        split2(v0, h0, l0); split2(v1, h1, l1);
        *(uint32_t*)(ohi + obase + i * 2) = pack_bf2(h0, h1);
        *(uint32_t*)(olo + obase + i * 2) = pack_bf2(l0, l1);
    }
}

// ---------------------------------------------------------------------------
// LayerNorm: fp32 out + bf16 hi/lo out
// ---------------------------------------------------------------------------
__global__ void __launch_bounds__(256) ln_kernel(
    const float* __restrict__ x, const float* __restrict__ w,
    const float* __restrict__ b, float* __restrict__ out,
    bf16* __restrict__ obh, bf16* __restrict__ obl)
{
    const int row = blockIdx.x;
    const int tid = threadIdx.x;
    const float* xr = x + (long)row * D_;

    float v[3], s = 0.f, s2 = 0.f;
    #pragma unroll
    for (int i = 0; i < 3; i++) {
        v[i] = xr[tid + i * 256];
        s += v[i];
        s2 = fmaf(v[i], v[i], s2);
    }
    s  = warp_sum(s);
    s2 = warp_sum(s2);
    __shared__ float sh[16];
    int wid = tid >> 5, lane = tid & 31;
    if (lane == 0) { sh[wid] = s; sh[8 + wid] = s2; }
    __syncthreads();
    if (tid == 0) {
        float a = 0.f, a2 = 0.f;
        #pragma unroll
        for (int i = 0; i < 8; i++) { a += sh[i]; a2 += sh[8 + i]; }
        sh[0] = a; sh[1] = a2;
    }
    __syncthreads();
    float mu  = sh[0] * (1.0f / D_);
    float var = sh[1] * (1.0f / D_) - mu * mu;
    float rs  = rsqrtf(var + 1e-5f);
    long rb = (long)row * D_;
    #pragma unroll
    for (int i = 0; i < 3; i++) {
        int c = tid + i * 256;
        float o = (v[i] - mu) * rs * w[c] + b[c];
        out[rb + c] = o;
        bf16 hi, lo; split2(o, hi, lo);
        obh[rb + c] = hi; obl[rb + c] = lo;
    }
}

// ---------------------------------------------------------------------------
// Launch
// ---------------------------------------------------------------------------
extern "C" void kernel_launch(void* const* d_in, const int* in_sizes, int n_in,
                              void* d_out, int out_size)
{
    const int*   x      = (const int*)  d_in[0];
    const int*   ignore = (const int*)  d_in[1];
    const float* bpe    = (const float*)d_in[2];
    const float* pe     = (const float*)d_in[3];
    const float* Wq     = (const float*)d_in[4];
    const float* bq     = (const float*)d_in[5];
    const float* Wk     = (const float*)d_in[6];
    const float* bk     = (const float*)d_in[7];
    const float* Wv     = (const float*)d_in[8];
    const float* bv     = (const float*)d_in[9];
    const float* Wo     = (const float*)d_in[10];
    const float* bo     = (const float*)d_in[11];
    const float* W1     = (const float*)d_in[12];
    const float* b1     = (const float*)d_in[13];
    const float* W2     = (const float*)d_in[14];
    const float* b2     = (const float*)d_in[15];
    const float* ln1w   = (const float*)d_in[16];
    const float* ln1b   = (const float*)d_in[17];
    const float* ln2w   = (const float*)d_in[18];
    const float* ln2b   = (const float*)d_in[19];
    const float* Wout   = (const float*)d_in[20];
    const float* bout   = (const float*)d_in[21];
    float* out = (float*)d_out;

    cudaFuncSetAttribute(attn_kernel,
        cudaFuncAttributeMaxDynamicSharedMemorySize, ATTN_SMEM);
    cudaFuncSetAttribute(mgemm_kernel<128, 0, false>,
        cudaFuncAttributeMaxDynamicSharedMemorySize, MG_SMEM_128);
    cudaFuncSetAttribute(mgemm_kernel<128, 3, false>,
        cudaFuncAttributeMaxDynamicSharedMemorySize, MG_SMEM_128);
    cudaFuncSetAttribute(mgemm_kernel<128, 0, true>,
        cudaFuncAttributeMaxDynamicSharedMemorySize, MG_SMEM_128);
    cudaFuncSetAttribute(mgemm_kernel<64, 1, false>,
        cudaFuncAttributeMaxDynamicSharedMemorySize, MG_SMEM_64);
    cudaFuncSetAttribute(mgemm_kernel<64, 2, false>,
        cudaFuncAttributeMaxDynamicSharedMemorySize, MG_SMEM_64);

    float *h, *qkv, *r, *h1, *bqkv;
    bf16 *hbh, *hbl, *abh, *abl, *h1bh, *h1bl, *tbh, *tbl;
    bf16 *wqkvh, *wqkvl, *woh, *wol, *w1h, *w1l, *w2h, *w2l, *wouth, *woutl;
    cudaGetSymbolAddress((void**)&h,    g_h);
    cudaGetSymbolAddress((void**)&qkv,  g_qkv);
    cudaGetSymbolAddress((void**)&r,    g_r);
    cudaGetSymbolAddress((void**)&h1,   g_h1);
    cudaGetSymbolAddress((void**)&hbh,  g_hb_hi);
    cudaGetSymbolAddress((void**)&hbl,  g_hb_lo);
    cudaGetSymbolAddress((void**)&abh,  g_ab_hi);
    cudaGetSymbolAddress((void**)&abl,  g_ab_lo);
    cudaGetSymbolAddress((void**)&h1bh, g_h1b_hi);
    cudaGetSymbolAddress((void**)&h1bl, g_h1b_lo);
    cudaGetSymbolAddress((void**)&tbh,  g_tb_hi);
    cudaGetSymbolAddress((void**)&tbl,  g_tb_lo);
    cudaGetSymbolAddress((void**)&wqkvh, g_wqkv_hi);
    cudaGetSymbolAddress((void**)&wqkvl, g_wqkv_lo);
    cudaGetSymbolAddress((void**)&woh,  g_wo_hi);
    cudaGetSymbolAddress((void**)&wol,  g_wo_lo);
    cudaGetSymbolAddress((void**)&w1h,  g_w1_hi);
    cudaGetSymbolAddress((void**)&w1l,  g_w1_lo);
    cudaGetSymbolAddress((void**)&w2h,  g_w2_hi);
    cudaGetSymbolAddress((void**)&w2l,  g_w2_lo);
    cudaGetSymbolAddress((void**)&wouth, g_wout_hi);
    cudaGetSymbolAddress((void**)&woutl, g_wout_lo);
    cudaGetSymbolAddress((void**)&bqkv, g_bqkv);

    dim3 pb(32, 8);
    prep_w_kernel<<<dim3(2, 24, L_ * H_), pb>>>(Wq, wqkvh, wqkvl,
        D_, HD_, (long)D_ * HD_, H_, (long)QKVN * D_, (long)HD_ * D_);
    prep_w_kernel<<<dim3(2, 24, L_ * H_), pb>>>(Wk,
        wqkvh + (long)D_ * D_, wqkvl + (long)D_ * D_,
        D_, HD_, (long)D_ * HD_, H_, (long)QKVN * D_, (long)HD_ * D_);
    prep_w_kernel<<<dim3(2, 24, L_ * H_), pb>>>(Wv,
        wqkvh + (long)2 * D_ * D_, wqkvl + (long)2 * D_ * D_,
        D_, HD_, (long)D_ * HD_, H_, (long)QKVN * D_, (long)HD_ * D_);
    prep_w_kernel<<<dim3(24, 24, L_), pb>>>(Wo, woh, wol,
        D_, D_, (long)D_ * D_, 1, (long)D_ * D_, 0);
    prep_w_kernel<<<dim3(96, 24, L_), pb>>>(W1, w1h, w1l,
        D_, F_, (long)D_ * F_, 1, (long)D_ * F_, 0);
    prep_w_kernel<<<dim3(24, 96, L_), pb>>>(W2, w2h, w2l,
        F_, D_, (long)F_ * D_, 1, (long)F_ * D_, 0);
    prep_w_kernel<<<dim3(1250, 24, 1), pb>>>(Wout, wouth, woutl,
        D_, V_, 0, 1, 0, 0);
    concat_bias_kernel<<<L_, 256>>>(bq, bk, bv, bqkv);

    embed_kernel<<<T_, 256>>>(x, bpe, pe, h, hbh, hbl);

    const dim3 gQKV(T_ / 128, QKVN / 128);  // 16 x 18
    const dim3 gD64(T_ / 64,  D_ / 128);    // 32 x 6 = 192
    const dim3 gF  (T_ / 128, F_ / 128);    // 16 x 24
    const dim3 gV  (T_ / 128, VPAD / 128);  // 16 x 313

    for (int l = 0; l < L_; l++) {
        long wq_off = (long)l * QKVN * D_;
        long wd_off = (long)l * D_ * D_;
        long wf_off = (long)l * D_ * F_;

        // qkv = h @ Wqkv + bqkv
        mgemm_kernel<128, 0, false><<<gQKV, 256, MG_SMEM_128>>>(
            hbh, hbl, wqkvh + wq_off, wqkvl + wq_off, bqkv + (long)l * QKVN,
            nullptr, qkv, nullptr, nullptr, D_, QKVN);

        attn_kernel<<<B_ * H_, 128, ATTN_SMEM>>>(qkv, ignore, abh, abl);

        // r = h + a @ Wo + bo
        mgemm_kernel<64, 1, false><<<gD64, 256, MG_SMEM_64>>>(
            abh, abl, woh + wd_off, wol + wd_off, bo + (long)l * D_,
            h, r, nullptr, nullptr, D_, D_);
        ln_kernel<<<T_, 256>>>(r, ln1w + (long)l * D_, ln1b + (long)l * D_,
                               h1, h1bh, h1bl);
        // t = h1 @ W1 + b1 (bf16-only output)
        mgemm_kernel<128, 3, false><<<gF, 256, MG_SMEM_128>>>(
            h1bh, h1bl, w1h + wf_off, w1l + wf_off, b1 + (long)l * F_,
            nullptr, nullptr, tbh, tbl, D_, F_);
        // r = h1 + gelu(t @ W2 + b2)
        mgemm_kernel<64, 2, false><<<gD64, 256, MG_SMEM_64>>>(
            tbh, tbl, w2h + wf_off, w2l + wf_off, b2 + (long)l * D_,
            h1, r, nullptr, nullptr, F_, D_);
        ln_kernel<<<T_, 256>>>(r, ln2w + (long)l * D_, ln2b + (long)l * D_,
                               h, hbh, hbl);
    }

    // logits = h @ Wout + bout
    mgemm_kernel<128, 0, true><<<gV, 256, MG_SMEM_128>>>(
        hbh, hbl, wouth, woutl, bout, nullptr, out, nullptr, nullptr, D_, V_);
}